// round 15
// baseline (speedup 1.0000x reference)
#include <cuda_runtime.h>
#include <cuda_fp16.h>
#include <mma.h>
#include <cstdint>

using namespace nvcuda;

#define N_NODES 100000
#define N_EDGESC 1600000
#define XDIM 1010
#define SUBJ 1000
#define H1 512
#define H2 256
#define DG 128

// ---------------- static device scratch ----------------
__device__ __half g_xs[(size_t)N_NODES * 1024];   // x hi (K padded to 1024)
__device__ __half g_w1h[1024 * H1];               // W1 hi
__device__ __half g_hs[(size_t)N_NODES * 512];    // h hi only
__device__ __half g_w23h[H1 * DG];                // folded W2@Wg hi only
__device__ float  g_c2[DG];
__device__ __half g_y2[(size_t)N_NODES * DG];     // y in fp16
__device__ int    g_deg[N_NODES];
__device__ int    g_off[N_NODES];
__device__ int    g_cur[N_NODES];
__device__ int    g_es[N_EDGESC];
__device__ int    g_bsum[128];
__device__ double g_acc;

// ---------------- helpers ----------------
__device__ __forceinline__ uint32_t smem_u32(const void* p) {
    uint32_t a;
    asm("{ .reg .u64 t; cvta.to.shared.u64 t, %1; cvt.u32.u64 %0, t; }" : "=r"(a) : "l"(p));
    return a;
}
#define CP_A16(dst, src, n) \
    asm volatile("cp.async.cg.shared.global [%0], [%1], 16, %2;" :: "r"(dst), "l"(src), "r"(n))
#define CP_COMMIT() asm volatile("cp.async.commit_group;" ::: "memory")
#define CP_WAIT0()  asm volatile("cp.async.wait_group 0;" ::: "memory")
#define CP_WAIT1()  asm volatile("cp.async.wait_group 1;" ::: "memory")

// ---------------- x -> fp16 hi (row range) ----------------
__global__ void k_splitx(const float* __restrict__ x, int row0, int row1) {
    long long total = (long long)(row1 - row0) * 512;
    for (long long id = (long long)blockIdx.x * blockDim.x + threadIdx.x;
         id < total; id += (long long)gridDim.x * blockDim.x) {
        int row = row0 + (int)(id >> 9);
        int col = (int)(id & 511) * 2;
        float2 v = make_float2(0.f, 0.f);
        if (col < SUBJ) v = *reinterpret_cast<const float2*>(&x[(size_t)row * XDIM + col]);
        *reinterpret_cast<__half2*>(&g_xs[(size_t)row * 1024 + col]) = __float22half2_rn(v);
    }
}

// ---------------- W1 -> fp16 hi ----------------
__global__ void k_splitw(const float* __restrict__ W1) {
    int id = blockIdx.x * blockDim.x + threadIdx.x;
    if (id >= 1024 * 256) return;
    int row = id >> 8;
    int col = (id & 255) * 2;
    float2 v = make_float2(0.f, 0.f);
    if (row < SUBJ) v = *reinterpret_cast<const float2*>(&W1[(size_t)row * H1 + col]);
    *reinterpret_cast<__half2*>(&g_w1h[row * H1 + col]) = __float22half2_rn(v);
}

// ---------------- init ----------------
__global__ void k_init() {
    int i = blockIdx.x * blockDim.x + threadIdx.x;
    if (i < N_NODES) g_deg[i] = 1;
    if (i == 0) g_acc = 0.0;
}

// ---------------- weight fold (fp16 hi) ----------------
__global__ void k_pre(const float* __restrict__ W2, const float* __restrict__ Wg,
                      const float* __restrict__ b2) {
    int k = blockIdx.x;
    int j = threadIdx.x;
    if (k < H1) {
        __shared__ float row[H2];
        for (int m = j; m < H2; m += 128) row[m] = W2[k * H2 + m];
        __syncthreads();
        float acc = 0.f;
        #pragma unroll 4
        for (int m = 0; m < H2; m++) acc += row[m] * Wg[m * DG + j];
        g_w23h[k * DG + j] = __float2half_rn(acc);
    } else {
        float acc = 0.f;
        for (int m = 0; m < H2; m++) acc += b2[m] * Wg[m * DG + j];
        g_c2[j] = acc;
    }
}

// ---------------- degree count ----------------
__global__ void k_deg(const int* __restrict__ ei) {
    for (int e = blockIdx.x * blockDim.x + threadIdx.x; e < N_EDGESC;
         e += gridDim.x * blockDim.x) {
        int dst = ei[N_EDGESC + e];
        dst = min(max(dst, 0), N_NODES - 1);
        atomicAdd(&g_deg[dst], 1);
    }
}

// ---------------- multi-block scan ----------------
#define SCAN_CHUNK 1024
#define SCAN_NBLK ((N_NODES + SCAN_CHUNK - 1) / SCAN_CHUNK)  // 98

__global__ void k_scan1() {
    __shared__ int wsum[32];
    int i = blockIdx.x * SCAN_CHUNK + threadIdx.x;
    int v = (i < N_NODES) ? (g_deg[i] - 1) : 0;
    #pragma unroll
    for (int o = 16; o; o >>= 1) v += __shfl_down_sync(0xffffffffu, v, o);
    int lane = threadIdx.x & 31, wid = threadIdx.x >> 5;
    if (lane == 0) wsum[wid] = v;
    __syncthreads();
    if (wid == 0) {
        int t = wsum[lane];
        #pragma unroll
        for (int o = 16; o; o >>= 1) t += __shfl_down_sync(0xffffffffu, t, o);
        if (lane == 0) g_bsum[blockIdx.x] = t;
    }
}

__global__ void k_scan2() {
    __shared__ int wtot[4];
    int tid = threadIdx.x, lane = tid & 31, wid = tid >> 5;
    int v = (tid < SCAN_NBLK) ? g_bsum[tid] : 0;
    int s = v;
    #pragma unroll
    for (int o = 1; o < 32; o <<= 1) {
        int t = __shfl_up_sync(0xffffffffu, s, o);
        if (lane >= o) s += t;
    }
    if (lane == 31) wtot[wid] = s;
    __syncthreads();
    int base = 0;
    for (int w = 0; w < wid; w++) base += wtot[w];
    if (tid < SCAN_NBLK) g_bsum[tid] = base + s - v;
}

__global__ void k_scan3() {
    __shared__ int wpre[32];
    int tid = threadIdx.x, lane = tid & 31, wid = tid >> 5;
    int i = blockIdx.x * SCAN_CHUNK + tid;
    int v = (i < N_NODES) ? (g_deg[i] - 1) : 0;
    int s = v;
    #pragma unroll
    for (int o = 1; o < 32; o <<= 1) {
        int t = __shfl_up_sync(0xffffffffu, s, o);
        if (lane >= o) s += t;
    }
    if (lane == 31) wpre[wid] = s;
    __syncthreads();
    if (wid == 0) {
        int t = wpre[lane];
        #pragma unroll
        for (int o = 1; o < 32; o <<= 1) {
            int u = __shfl_up_sync(0xffffffffu, t, o);
            if (lane >= o) t += u;
        }
        wpre[lane] = t;
    }
    __syncthreads();
    int excl = s - v + (wid > 0 ? wpre[wid - 1] : 0) + g_bsum[blockIdx.x];
    if (i < N_NODES) { g_off[i] = excl; g_cur[i] = excl; }
}

// ---------------- CSR fill ----------------
__global__ void k_fill(const int* __restrict__ ei) {
    for (int e = blockIdx.x * blockDim.x + threadIdx.x; e < N_EDGESC;
         e += gridDim.x * blockDim.x) {
        int src = ei[e];
        int dst = ei[N_EDGESC + e];
        src = min(max(src, 0), N_NODES - 1);
        dst = min(max(dst, 0), N_NODES - 1);
        int pos = atomicAdd(&g_cur[dst], 1);
        g_es[pos] = src;
    }
}

// ================= GEMM1: BM=128 BN=128 BK=64, 3-stage, 1-term fp16 =================
#define LDA1 72
#define LDB1 136
#define LDC1 136
#define S1_OFF_BH 18432
#define STG1 35840
#define DYN1 107520
#define G1_MBLK ((N_NODES + 127) / 128)   // 782

__device__ __forceinline__ void g1_issue(char* st, int tid, int kt, int rows_left,
                                         const __half* Asrc, const __half* Bsrc) {
    const int k0 = kt * 64;
    const uint32_t ah = smem_u32(st);
    const uint32_t bh = ah + S1_OFF_BH;
    #pragma unroll
    for (int p = 0; p < 4; p++) {
        int idx = tid + p * 256;
        int row = idx >> 3;
        int ch = idx & 7;
        int n = (row < rows_left) ? 16 : 0;
        const __half* s = Asrc + (size_t)row * 1024 + k0 + ch * 8;
        CP_A16(ah + row * (LDA1 * 2) + ch * 16, s, n);
    }
    #pragma unroll
    for (int p = 0; p < 4; p++) {
        int idx = tid + p * 256;
        int row = idx >> 4;
        int ch = idx & 15;
        const __half* sh = Bsrc + (size_t)(k0 + row) * H1 + ch * 8;
        CP_A16(bh + row * (LDB1 * 2) + ch * 16, sh, 16);
    }
    CP_COMMIT();
}

__global__ __launch_bounds__(256) void k_gemm1(const float* __restrict__ b1, int mb0) {
    extern __shared__ __align__(128) char dyn[];
    const int bx = blockIdx.x;
    const int i0 = (mb0 + (bx >> 2)) * 128;
    const int n0 = (bx & 3) * 128;
    const int tid = threadIdx.x;
    const int wid = tid >> 5;
    const int warpM = wid & 3, warpN = wid >> 2;
    const int rows_left = N_NODES - i0;
    const __half* Asrc = g_xs + (size_t)i0 * 1024;
    const __half* Bsrc = g_w1h + n0;

    wmma::fragment<wmma::accumulator, 16, 16, 16, float> acc[2][4];
    #pragma unroll
    for (int m = 0; m < 2; m++)
        #pragma unroll
        for (int n = 0; n < 4; n++) wmma::fill_fragment(acc[m][n], 0.f);

    g1_issue(dyn, tid, 0, rows_left, Asrc, Bsrc);
    g1_issue(dyn + STG1, tid, 1, rows_left, Asrc, Bsrc);

    for (int kt = 0; kt < 16; kt++) {
        if (kt < 14) CP_WAIT1(); else CP_WAIT0();
        __syncthreads();
        if (kt + 2 < 16) g1_issue(dyn + ((kt + 2) % 3) * STG1, tid, kt + 2, rows_left, Asrc, Bsrc);
        char* st = dyn + (kt % 3) * STG1;
        __half (*Ah)[LDA1] = reinterpret_cast<__half(*)[LDA1]>(st);
        __half (*Bh)[LDB1] = reinterpret_cast<__half(*)[LDB1]>(st + S1_OFF_BH);
        #pragma unroll
        for (int kk = 0; kk < 64; kk += 16) {
            wmma::fragment<wmma::matrix_a, 16, 16, 16, __half, wmma::row_major> afH[2];
            #pragma unroll
            for (int m = 0; m < 2; m++)
                wmma::load_matrix_sync(afH[m], &Ah[warpM * 32 + m * 16][kk], LDA1);
            #pragma unroll
            for (int n = 0; n < 4; n++) {
                wmma::fragment<wmma::matrix_b, 16, 16, 16, __half, wmma::row_major> bfH;
                wmma::load_matrix_sync(bfH, &Bh[kk][warpN * 64 + n * 16], LDB1);
                #pragma unroll
                for (int m = 0; m < 2; m++)
                    wmma::mma_sync(acc[m][n], afH[m], bfH, acc[m][n]);
            }
        }
    }

    __syncthreads();
    float (*Cs)[LDC1] = reinterpret_cast<float(*)[LDC1]>(dyn);
    #pragma unroll
    for (int m = 0; m < 2; m++)
        #pragma unroll
        for (int n = 0; n < 4; n++)
            wmma::store_matrix_sync(&Cs[warpM * 32 + m * 16][warpN * 64 + n * 16],
                                    acc[m][n], LDC1, wmma::mem_row_major);
    __syncthreads();
    #pragma unroll
    for (int q = 0; q < 32; q++) {
        int idx = q * 256 + tid;
        int r = idx >> 6, c2 = (idx & 63) * 2;
        int gi = i0 + r;
        if (gi < N_NODES) {
            float2 v;
            v.x = fmaxf(Cs[r][c2] + __ldg(&b1[n0 + c2]), 0.f);
            v.y = fmaxf(Cs[r][c2 + 1] + __ldg(&b1[n0 + c2 + 1]), 0.f);
            *reinterpret_cast<__half2*>(&g_hs[(size_t)gi * 512 + n0 + c2]) = __float22half2_rn(v);
        }
    }
}

// ================= GEMM2 (1-term, BK=32, 3-stage) =================
#define LDA2 40
#define LDB2 136
#define S2_OFF_BH 10240
#define STG2 18944
#define DYN2 69632

__device__ __forceinline__ void g2_issue(char* st, int tid, int kt, int rows_left,
                                         const __half* Asrc) {
    const int k0 = kt * 32;
    const uint32_t ah = smem_u32(st);
    const uint32_t bh = ah + S2_OFF_BH;
    #pragma unroll
    for (int p = 0; p < 2; p++) {
        int idx = tid + p * 256;
        int row = idx >> 2;
        int ch = idx & 3;
        int n = (row < rows_left) ? 16 : 0;
        const __half* s = Asrc + (size_t)row * 512 + k0 + ch * 8;
        CP_A16(ah + row * (LDA2 * 2) + ch * 16, s, n);
    }
    #pragma unroll
    for (int p = 0; p < 2; p++) {
        int idx = tid + p * 256;
        int row = idx >> 4;
        int ch = idx & 15;
        const __half* sh = g_w23h + (size_t)(k0 + row) * DG + ch * 8;
        CP_A16(bh + row * (LDB2 * 2) + ch * 16, sh, 16);
    }
    CP_COMMIT();
}

__global__ __launch_bounds__(256) void k_gemm2(const float* __restrict__ x,
                                               const float* __restrict__ Wg) {
    extern __shared__ __align__(128) char dyn[];
    __shared__ float demoS[128][10];
    __shared__ float WgbS[10][DG];
    __shared__ float c2S[DG];

    const int i0 = blockIdx.x * 128;
    const int tid = threadIdx.x;
    const int wid = tid >> 5;
    const int warpM = wid & 3, warpN = wid >> 2;
    const int rows_left = N_NODES - i0;
    const __half* Asrc = g_hs + (size_t)i0 * 512;

    for (int idx = tid; idx < 128 * 10; idx += 256) {
        int r = idx / 10, t = idx % 10;
        int gi = i0 + r;
        demoS[r][t] = (gi < N_NODES) ? x[(size_t)gi * XDIM + SUBJ + t] : 0.f;
    }
    for (int idx = tid; idx < 10 * DG; idx += 256) {
        int t = idx >> 7, c = idx & 127;
        WgbS[t][c] = Wg[(H2 + t) * DG + c];
    }
    if (tid < DG) c2S[tid] = g_c2[tid];

    wmma::fragment<wmma::accumulator, 16, 16, 16, float> acc[2][4];
    #pragma unroll
    for (int m = 0; m < 2; m++)
        #pragma unroll
        for (int n = 0; n < 4; n++) wmma::fill_fragment(acc[m][n], 0.f);

    g2_issue(dyn, tid, 0, rows_left, Asrc);
    g2_issue(dyn + STG2, tid, 1, rows_left, Asrc);

    for (int kt = 0; kt < 16; kt++) {
        if (kt < 14) CP_WAIT1(); else CP_WAIT0();
        __syncthreads();
        if (kt + 2 < 16) g2_issue(dyn + ((kt + 2) % 3) * STG2, tid, kt + 2, rows_left, Asrc);
        char* st = dyn + (kt % 3) * STG2;
        __half (*Ah)[LDA2] = reinterpret_cast<__half(*)[LDA2]>(st);
        __half (*Bh)[LDB2] = reinterpret_cast<__half(*)[LDB2]>(st + S2_OFF_BH);
        #pragma unroll
        for (int kk = 0; kk < 32; kk += 16) {
            wmma::fragment<wmma::matrix_a, 16, 16, 16, __half, wmma::row_major> afH[2];
            #pragma unroll
            for (int m = 0; m < 2; m++)
                wmma::load_matrix_sync(afH[m], &Ah[warpM * 32 + m * 16][kk], LDA2);
            #pragma unroll
            for (int n = 0; n < 4; n++) {
                wmma::fragment<wmma::matrix_b, 16, 16, 16, __half, wmma::row_major> bfH;
                wmma::load_matrix_sync(bfH, &Bh[kk][warpN * 64 + n * 16], LDB2);
                #pragma unroll
                for (int m = 0; m < 2; m++)
                    wmma::mma_sync(acc[m][n], afH[m], bfH, acc[m][n]);
            }
        }
    }

    __syncthreads();
    float (*Cs)[LDC1] = reinterpret_cast<float(*)[LDC1]>(dyn);
    #pragma unroll
    for (int m = 0; m < 2; m++)
        #pragma unroll
        for (int n = 0; n < 4; n++)
            wmma::store_matrix_sync(&Cs[warpM * 32 + m * 16][warpN * 64 + n * 16],
                                    acc[m][n], LDC1, wmma::mem_row_major);
    __syncthreads();
    #pragma unroll
    for (int q = 0; q < 32; q++) {
        int idx = q * 256 + tid;
        int r = idx >> 6, c2 = (idx & 63) * 2;
        int gi = i0 + r;
        if (gi < N_NODES) {
            float v0 = Cs[r][c2] + c2S[c2];
            float v1 = Cs[r][c2 + 1] + c2S[c2 + 1];
            #pragma unroll
            for (int t = 0; t < 10; t++) {
                float d = demoS[r][t];
                v0 += d * WgbS[t][c2];
                v1 += d * WgbS[t][c2 + 1];
            }
            float dinv = rsqrtf((float)g_deg[gi]);
            *reinterpret_cast<__half2*>(&g_y2[(size_t)gi * DG + c2]) =
                __floats2half2_rn(dinv * v0, dinv * v1);
        }
    }
}

// ---------------- gather (fp16 y) + fused epilogue ----------------
__global__ __launch_bounds__(256) void k_gather(const float* __restrict__ bg,
                                                const float* __restrict__ Wo) {
    int wid = threadIdx.x >> 5, lane = threadIdx.x & 31;
    int node = blockIdx.x * 8 + wid;
    float dot = 0.f;
    if (node < N_NODES) {
        int deg = g_deg[node];
        int beg = g_off[node];
        int cnt = deg - 1;
        float2 raw = *reinterpret_cast<const float2*>(&g_y2[(size_t)node * DG + lane * 4]);
        __half2 h0 = *reinterpret_cast<__half2*>(&raw.x);
        __half2 h1 = *reinterpret_cast<__half2*>(&raw.y);
        float2 f0 = __half22float2(h0), f1 = __half22float2(h1);
        float4 a = make_float4(f0.x, f0.y, f1.x, f1.y);
        #pragma unroll 4
        for (int j = 0; j < cnt; j++) {
            int s = __ldg(&g_es[beg + j]);
            float2 rw = *reinterpret_cast<const float2*>(&g_y2[(size_t)s * DG + lane * 4]);
            __half2 g0 = *reinterpret_cast<__half2*>(&rw.x);
            __half2 g1 = *reinterpret_cast<__half2*>(&rw.y);
            float2 e0 = __half22float2(g0), e1 = __half22float2(g1);
            a.x += e0.x; a.y += e0.y; a.z += e1.x; a.w += e1.y;
        }
        float dinv = rsqrtf((float)deg);
        float4 bgv = *reinterpret_cast<const float4*>(&bg[lane * 4]);
        float4 wv = *reinterpret_cast<const float4*>(&Wo[lane * 4]);
        dot += fmaxf(dinv * a.x + bgv.x, 0.f) * wv.x;
        dot += fmaxf(dinv * a.y + bgv.y, 0.f) * wv.y;
        dot += fmaxf(dinv * a.z + bgv.z, 0.f) * wv.z;
        dot += fmaxf(dinv * a.w + bgv.w, 0.f) * wv.w;
    }
    #pragma unroll
    for (int o = 16; o; o >>= 1) dot += __shfl_down_sync(0xffffffffu, dot, o);
    __shared__ float part[8];
    if (lane == 0) part[wid] = dot;
    __syncthreads();
    if (threadIdx.x == 0) {
        float s = 0.f;
        #pragma unroll
        for (int w = 0; w < 8; w++) s += part[w];
        atomicAdd(&g_acc, (double)s);
    }
}

__global__ void k_fin(const float* __restrict__ bo, float* __restrict__ out) {
    out[0] = (float)(g_acc * (1.0 / (double)N_NODES) + (double)bo[0]);
}

// ---------------- launch (chunked splitx || gemm1, plus edge-chain stream) ----------------
#define NCHUNK 4
static const int c_mb[NCHUNK + 1] = {0, 196, 392, 588, G1_MBLK};

extern "C" void kernel_launch(void* const* d_in, const int* in_sizes, int n_in,
                              void* d_out, int out_size) {
    const float* x  = (const float*)d_in[0];
    const int*   ei = (const int*)d_in[1];
    const float* W1 = (const float*)d_in[2];
    const float* b1 = (const float*)d_in[3];
    const float* W2 = (const float*)d_in[4];
    const float* b2 = (const float*)d_in[5];
    const float* Wg = (const float*)d_in[6];
    const float* bg = (const float*)d_in[7];
    const float* Wo = (const float*)d_in[8];
    const float* bo = (const float*)d_in[9];
    float* out = (float*)d_out;

    static cudaStream_t s1 = nullptr, s2 = nullptr;
    static cudaEvent_t eFork = nullptr, eJoin = nullptr, eX[NCHUNK];
    if (s1 == nullptr) {
        cudaStreamCreateWithFlags(&s1, cudaStreamNonBlocking);
        cudaStreamCreateWithFlags(&s2, cudaStreamNonBlocking);
        cudaEventCreateWithFlags(&eFork, cudaEventDisableTiming);
        cudaEventCreateWithFlags(&eJoin, cudaEventDisableTiming);
        for (int c = 0; c < NCHUNK; c++)
            cudaEventCreateWithFlags(&eX[c], cudaEventDisableTiming);
        cudaFuncSetAttribute(k_gemm1, cudaFuncAttributeMaxDynamicSharedMemorySize, DYN1);
        cudaFuncSetAttribute(k_gemm2, cudaFuncAttributeMaxDynamicSharedMemorySize, DYN2);
    }

    // fork
    cudaEventRecord(eFork, 0);
    cudaStreamWaitEvent(s1, eFork, 0);
    cudaStreamWaitEvent(s2, eFork, 0);

    // s2: splitx chunks (sequential on s2, each records an event)
    for (int c = 0; c < NCHUNK; c++) {
        int r0 = c_mb[c] * 128;
        int r1 = c_mb[c + 1] * 128;
        if (r1 > N_NODES) r1 = N_NODES;
        k_splitx<<<1024, 256, 0, s2>>>(x, r0, r1);
        cudaEventRecord(eX[c], s2);
    }

    // s1: edge prep + weight fold
    k_init<<<(N_NODES + 255) / 256, 256, 0, s1>>>();
    k_pre<<<H1 + 1, 128, 0, s1>>>(W2, Wg, b2);
    k_deg<<<4096, 256, 0, s1>>>(ei);
    k_scan1<<<SCAN_NBLK, SCAN_CHUNK, 0, s1>>>();
    k_scan2<<<1, 128, 0, s1>>>();
    k_scan3<<<SCAN_NBLK, SCAN_CHUNK, 0, s1>>>();
    k_fill<<<4096, 256, 0, s1>>>(ei);
    cudaEventRecord(eJoin, s1);

    // main: W1 convert, then gemm1 chunk-by-chunk as x chunks land
    k_splitw<<<(1024 * 256 + 255) / 256, 256>>>(W1);
    for (int c = 0; c < NCHUNK; c++) {
        cudaStreamWaitEvent(0, eX[c], 0);
        int mblks = c_mb[c + 1] - c_mb[c];
        k_gemm1<<<mblks * 4, 256, DYN1>>>(b1, c_mb[c]);
    }

    // join: gemm2 needs g_deg/g_w23h/g_c2; gather needs g_off/g_es
    cudaStreamWaitEvent(0, eJoin, 0);
    k_gemm2<<<(N_NODES + 127) / 128, 256, DYN2>>>(x, Wg);
    k_gather<<<(N_NODES + 7) / 8, 256>>>(bg, Wo);
    k_fin<<<1, 1>>>(bo, out);
}

// round 16
// speedup vs baseline: 1.0025x; 1.0025x over previous
#include <cuda_runtime.h>
#include <cuda_fp16.h>
#include <mma.h>
#include <cstdint>

using namespace nvcuda;

#define N_NODES 100000
#define N_EDGESC 1600000
#define XDIM 1010
#define SUBJ 1000
#define H1 512
#define H2 256
#define DG 128

// ---------------- static device scratch ----------------
__device__ __half g_xs[(size_t)N_NODES * 1024];   // x hi (K padded to 1024)
__device__ __half g_w1h[1024 * H1];               // W1 hi
__device__ __half g_hs[(size_t)N_NODES * 512];    // h hi only
__device__ __half g_w23h[H1 * DG];                // folded W2@Wg hi only
__device__ float  g_c2[DG];
__device__ __half g_y2[(size_t)N_NODES * DG];     // y in fp16
__device__ int    g_deg[N_NODES];
__device__ int    g_off[N_NODES];
__device__ int    g_cur[N_NODES];
__device__ int    g_es[N_EDGESC];
__device__ int    g_bsum[128];
__device__ double g_acc;

// ---------------- helpers ----------------
__device__ __forceinline__ uint32_t smem_u32(const void* p) {
    uint32_t a;
    asm("{ .reg .u64 t; cvta.to.shared.u64 t, %1; cvt.u32.u64 %0, t; }" : "=r"(a) : "l"(p));
    return a;
}
#define CP_A16(dst, src, n) \
    asm volatile("cp.async.cg.shared.global [%0], [%1], 16, %2;" :: "r"(dst), "l"(src), "r"(n))
#define CP_COMMIT() asm volatile("cp.async.commit_group;" ::: "memory")
#define CP_WAIT0()  asm volatile("cp.async.wait_group 0;" ::: "memory")
#define CP_WAIT1()  asm volatile("cp.async.wait_group 1;" ::: "memory")

// ---------------- x -> fp16 hi ----------------
__global__ void k_splitx(const float* __restrict__ x) {
    for (long long id = (long long)blockIdx.x * blockDim.x + threadIdx.x;
         id < (long long)N_NODES * 512; id += (long long)gridDim.x * blockDim.x) {
        int row = (int)(id >> 9);
        int col = (int)(id & 511) * 2;
        float2 v = make_float2(0.f, 0.f);
        if (col < SUBJ) v = *reinterpret_cast<const float2*>(&x[(size_t)row * XDIM + col]);
        *reinterpret_cast<__half2*>(&g_xs[(size_t)row * 1024 + col]) = __float22half2_rn(v);
    }
}

// ---------------- W1 -> fp16 hi ----------------
__global__ void k_splitw(const float* __restrict__ W1) {
    int id = blockIdx.x * blockDim.x + threadIdx.x;
    if (id >= 1024 * 256) return;
    int row = id >> 8;
    int col = (id & 255) * 2;
    float2 v = make_float2(0.f, 0.f);
    if (row < SUBJ) v = *reinterpret_cast<const float2*>(&W1[(size_t)row * H1 + col]);
    *reinterpret_cast<__half2*>(&g_w1h[row * H1 + col]) = __float22half2_rn(v);
}

// ---------------- init ----------------
__global__ void k_init() {
    int i = blockIdx.x * blockDim.x + threadIdx.x;
    if (i < N_NODES) g_deg[i] = 1;
    if (i == 0) g_acc = 0.0;
}

// ---------------- weight fold (fp16 hi) ----------------
__global__ void k_pre(const float* __restrict__ W2, const float* __restrict__ Wg,
                      const float* __restrict__ b2) {
    int k = blockIdx.x;
    int j = threadIdx.x;
    if (k < H1) {
        __shared__ float row[H2];
        for (int m = j; m < H2; m += 128) row[m] = W2[k * H2 + m];
        __syncthreads();
        float acc = 0.f;
        #pragma unroll 4
        for (int m = 0; m < H2; m++) acc += row[m] * Wg[m * DG + j];
        g_w23h[k * DG + j] = __float2half_rn(acc);
    } else {
        float acc = 0.f;
        for (int m = 0; m < H2; m++) acc += b2[m] * Wg[m * DG + j];
        g_c2[j] = acc;
    }
}

// ---------------- degree count ----------------
__global__ void k_deg(const int* __restrict__ ei) {
    for (int e = blockIdx.x * blockDim.x + threadIdx.x; e < N_EDGESC;
         e += gridDim.x * blockDim.x) {
        int dst = ei[N_EDGESC + e];
        dst = min(max(dst, 0), N_NODES - 1);
        atomicAdd(&g_deg[dst], 1);
    }
}

// ---------------- multi-block scan ----------------
#define SCAN_CHUNK 1024
#define SCAN_NBLK ((N_NODES + SCAN_CHUNK - 1) / SCAN_CHUNK)  // 98

__global__ void k_scan1() {
    __shared__ int wsum[32];
    int i = blockIdx.x * SCAN_CHUNK + threadIdx.x;
    int v = (i < N_NODES) ? (g_deg[i] - 1) : 0;
    #pragma unroll
    for (int o = 16; o; o >>= 1) v += __shfl_down_sync(0xffffffffu, v, o);
    int lane = threadIdx.x & 31, wid = threadIdx.x >> 5;
    if (lane == 0) wsum[wid] = v;
    __syncthreads();
    if (wid == 0) {
        int t = wsum[lane];
        #pragma unroll
        for (int o = 16; o; o >>= 1) t += __shfl_down_sync(0xffffffffu, t, o);
        if (lane == 0) g_bsum[blockIdx.x] = t;
    }
}

__global__ void k_scan2() {
    __shared__ int wtot[4];
    int tid = threadIdx.x, lane = tid & 31, wid = tid >> 5;
    int v = (tid < SCAN_NBLK) ? g_bsum[tid] : 0;
    int s = v;
    #pragma unroll
    for (int o = 1; o < 32; o <<= 1) {
        int t = __shfl_up_sync(0xffffffffu, s, o);
        if (lane >= o) s += t;
    }
    if (lane == 31) wtot[wid] = s;
    __syncthreads();
    int base = 0;
    for (int w = 0; w < wid; w++) base += wtot[w];
    if (tid < SCAN_NBLK) g_bsum[tid] = base + s - v;
}

__global__ void k_scan3() {
    __shared__ int wpre[32];
    int tid = threadIdx.x, lane = tid & 31, wid = tid >> 5;
    int i = blockIdx.x * SCAN_CHUNK + tid;
    int v = (i < N_NODES) ? (g_deg[i] - 1) : 0;
    int s = v;
    #pragma unroll
    for (int o = 1; o < 32; o <<= 1) {
        int t = __shfl_up_sync(0xffffffffu, s, o);
        if (lane >= o) s += t;
    }
    if (lane == 31) wpre[wid] = s;
    __syncthreads();
    if (wid == 0) {
        int t = wpre[lane];
        #pragma unroll
        for (int o = 1; o < 32; o <<= 1) {
            int u = __shfl_up_sync(0xffffffffu, t, o);
            if (lane >= o) t += u;
        }
        wpre[lane] = t;
    }
    __syncthreads();
    int excl = s - v + (wid > 0 ? wpre[wid - 1] : 0) + g_bsum[blockIdx.x];
    if (i < N_NODES) { g_off[i] = excl; g_cur[i] = excl; }
}

// ---------------- CSR fill ----------------
__global__ void k_fill(const int* __restrict__ ei) {
    for (int e = blockIdx.x * blockDim.x + threadIdx.x; e < N_EDGESC;
         e += gridDim.x * blockDim.x) {
        int src = ei[e];
        int dst = ei[N_EDGESC + e];
        src = min(max(src, 0), N_NODES - 1);
        dst = min(max(dst, 0), N_NODES - 1);
        int pos = atomicAdd(&g_cur[dst], 1);
        g_es[pos] = src;
    }
}

// ================= GEMM1: BM=256 BN=128 BK=64, 512 threads, 3-stage, 1-term =================
// 16 warps: 8(M) x 2(N), warp tile 32x64. 1 CTA/SM, 16 warps/SM (same as before).
// stage: AH[256x72] 36864 | BH[64x136] 17408 => 54272; x3 = 162816.
// epilogue Cs float[256][136] = 139264 < 162816.
#define LDA1 72
#define LDB1 136
#define LDC1 136
#define S1_OFF_BH 36864
#define STG1 54272
#define DYN1 162816
#define G1_MBLK ((N_NODES + 255) / 256)   // 391

__device__ __forceinline__ void g1_issue(char* st, int tid, int kt, int rows_left,
                                         const __half* Asrc, const __half* Bsrc) {
    const int k0 = kt * 64;
    const uint32_t ah = smem_u32(st);
    const uint32_t bh = ah + S1_OFF_BH;
    // A: 256 rows x 8 chunks of 16B = 2048 tasks, 4/thread
    #pragma unroll
    for (int p = 0; p < 4; p++) {
        int idx = tid + p * 512;
        int row = idx >> 3;
        int ch = idx & 7;
        int n = (row < rows_left) ? 16 : 0;
        const __half* s = Asrc + (size_t)row * 1024 + k0 + ch * 8;
        CP_A16(ah + row * (LDA1 * 2) + ch * 16, s, n);
    }
    // B: 64 rows x 16 chunks of 16B = 1024 tasks, 2/thread
    #pragma unroll
    for (int p = 0; p < 2; p++) {
        int idx = tid + p * 512;
        int row = idx >> 4;
        int ch = idx & 15;
        const __half* sh = Bsrc + (size_t)(k0 + row) * H1 + ch * 8;
        CP_A16(bh + row * (LDB1 * 2) + ch * 16, sh, 16);
    }
    CP_COMMIT();
}

__global__ __launch_bounds__(512) void k_gemm1(const float* __restrict__ b1) {
    extern __shared__ __align__(128) char dyn[];
    const int bx = blockIdx.x;
    const int i0 = (bx >> 2) * 256;
    const int n0 = (bx & 3) * 128;
    const int tid = threadIdx.x;
    const int wid = tid >> 5;
    const int warpM = wid & 7, warpN = wid >> 3;   // 8x2 warps, warp tile 32x64
    const int rows_left = N_NODES - i0;
    const __half* Asrc = g_xs + (size_t)i0 * 1024;
    const __half* Bsrc = g_w1h + n0;

    wmma::fragment<wmma::accumulator, 16, 16, 16, float> acc[2][4];
    #pragma unroll
    for (int m = 0; m < 2; m++)
        #pragma unroll
        for (int n = 0; n < 4; n++) wmma::fill_fragment(acc[m][n], 0.f);

    g1_issue(dyn, tid, 0, rows_left, Asrc, Bsrc);
    g1_issue(dyn + STG1, tid, 1, rows_left, Asrc, Bsrc);

    for (int kt = 0; kt < 16; kt++) {
        if (kt < 14) CP_WAIT1(); else CP_WAIT0();
        __syncthreads();
        if (kt + 2 < 16) g1_issue(dyn + ((kt + 2) % 3) * STG1, tid, kt + 2, rows_left, Asrc, Bsrc);
        char* st = dyn + (kt % 3) * STG1;
        __half (*Ah)[LDA1] = reinterpret_cast<__half(*)[LDA1]>(st);
        __half (*Bh)[LDB1] = reinterpret_cast<__half(*)[LDB1]>(st + S1_OFF_BH);
        #pragma unroll
        for (int kk = 0; kk < 64; kk += 16) {
            wmma::fragment<wmma::matrix_a, 16, 16, 16, __half, wmma::row_major> afH[2];
            #pragma unroll
            for (int m = 0; m < 2; m++)
                wmma::load_matrix_sync(afH[m], &Ah[warpM * 32 + m * 16][kk], LDA1);
            #pragma unroll
            for (int n = 0; n < 4; n++) {
                wmma::fragment<wmma::matrix_b, 16, 16, 16, __half, wmma::row_major> bfH;
                wmma::load_matrix_sync(bfH, &Bh[kk][warpN * 64 + n * 16], LDB1);
                #pragma unroll
                for (int m = 0; m < 2; m++)
                    wmma::mma_sync(acc[m][n], afH[m], bfH, acc[m][n]);
            }
        }
    }

    __syncthreads();
    float (*Cs)[LDC1] = reinterpret_cast<float(*)[LDC1]>(dyn);
    #pragma unroll
    for (int m = 0; m < 2; m++)
        #pragma unroll
        for (int n = 0; n < 4; n++)
            wmma::store_matrix_sync(&Cs[warpM * 32 + m * 16][warpN * 64 + n * 16],
                                    acc[m][n], LDC1, wmma::mem_row_major);
    __syncthreads();
    // 256 rows x 64 half2 pairs = 16384 tasks, 32/thread
    #pragma unroll
    for (int q = 0; q < 32; q++) {
        int idx = q * 512 + tid;
        int r = idx >> 6, c2 = (idx & 63) * 2;
        int gi = i0 + r;
        if (gi < N_NODES) {
            float2 v;
            v.x = fmaxf(Cs[r][c2] + __ldg(&b1[n0 + c2]), 0.f);
            v.y = fmaxf(Cs[r][c2 + 1] + __ldg(&b1[n0 + c2 + 1]), 0.f);
            *reinterpret_cast<__half2*>(&g_hs[(size_t)gi * 512 + n0 + c2]) = __float22half2_rn(v);
        }
    }
}

// ================= GEMM2 (1-term, BK=32, 3-stage, 256 threads) =================
#define LDA2 40
#define LDB2 136
#define S2_OFF_BH 10240
#define STG2 18944
#define DYN2 69632

__device__ __forceinline__ void g2_issue(char* st, int tid, int kt, int rows_left,
                                         const __half* Asrc) {
    const int k0 = kt * 32;
    const uint32_t ah = smem_u32(st);
    const uint32_t bh = ah + S2_OFF_BH;
    #pragma unroll
    for (int p = 0; p < 2; p++) {
        int idx = tid + p * 256;
        int row = idx >> 2;
        int ch = idx & 3;
        int n = (row < rows_left) ? 16 : 0;
        const __half* s = Asrc + (size_t)row * 512 + k0 + ch * 8;
        CP_A16(ah + row * (LDA2 * 2) + ch * 16, s, n);
    }
    #pragma unroll
    for (int p = 0; p < 2; p++) {
        int idx = tid + p * 256;
        int row = idx >> 4;
        int ch = idx & 15;
        const __half* sh = g_w23h + (size_t)(k0 + row) * DG + ch * 8;
        CP_A16(bh + row * (LDB2 * 2) + ch * 16, sh, 16);
    }
    CP_COMMIT();
}

__global__ __launch_bounds__(256) void k_gemm2(const float* __restrict__ x,
                                               const float* __restrict__ Wg) {
    extern __shared__ __align__(128) char dyn[];
    __shared__ float demoS[128][10];
    __shared__ float WgbS[10][DG];
    __shared__ float c2S[DG];

    const int i0 = blockIdx.x * 128;
    const int tid = threadIdx.x;
    const int wid = tid >> 5;
    const int warpM = wid & 3, warpN = wid >> 2;
    const int rows_left = N_NODES - i0;
    const __half* Asrc = g_hs + (size_t)i0 * 512;

    for (int idx = tid; idx < 128 * 10; idx += 256) {
        int r = idx / 10, t = idx % 10;
        int gi = i0 + r;
        demoS[r][t] = (gi < N_NODES) ? x[(size_t)gi * XDIM + SUBJ + t] : 0.f;
    }
    for (int idx = tid; idx < 10 * DG; idx += 256) {
        int t = idx >> 7, c = idx & 127;
        WgbS[t][c] = Wg[(H2 + t) * DG + c];
    }
    if (tid < DG) c2S[tid] = g_c2[tid];

    wmma::fragment<wmma::accumulator, 16, 16, 16, float> acc[2][4];
    #pragma unroll
    for (int m = 0; m < 2; m++)
        #pragma unroll
        for (int n = 0; n < 4; n++) wmma::fill_fragment(acc[m][n], 0.f);

    g2_issue(dyn, tid, 0, rows_left, Asrc);
    g2_issue(dyn + STG2, tid, 1, rows_left, Asrc);

    for (int kt = 0; kt < 16; kt++) {
        if (kt < 14) CP_WAIT1(); else CP_WAIT0();
        __syncthreads();
        if (kt + 2 < 16) g2_issue(dyn + ((kt + 2) % 3) * STG2, tid, kt + 2, rows_left, Asrc);
        char* st = dyn + (kt % 3) * STG2;
        __half (*Ah)[LDA2] = reinterpret_cast<__half(*)[LDA2]>(st);
        __half (*Bh)[LDB2] = reinterpret_cast<__half(*)[LDB2]>(st + S2_OFF_BH);
        #pragma unroll
        for (int kk = 0; kk < 32; kk += 16) {
            wmma::fragment<wmma::matrix_a, 16, 16, 16, __half, wmma::row_major> afH[2];
            #pragma unroll
            for (int m = 0; m < 2; m++)
                wmma::load_matrix_sync(afH[m], &Ah[warpM * 32 + m * 16][kk], LDA2);
            #pragma unroll
            for (int n = 0; n < 4; n++) {
                wmma::fragment<wmma::matrix_b, 16, 16, 16, __half, wmma::row_major> bfH;
                wmma::load_matrix_sync(bfH, &Bh[kk][warpN * 64 + n * 16], LDB2);
                #pragma unroll
                for (int m = 0; m < 2; m++)
                    wmma::mma_sync(acc[m][n], afH[m], bfH, acc[m][n]);
            }
        }
    }

    __syncthreads();
    float (*Cs)[LDC1] = reinterpret_cast<float(*)[LDC1]>(dyn);
    #pragma unroll
    for (int m = 0; m < 2; m++)
        #pragma unroll
        for (int n = 0; n < 4; n++)
            wmma::store_matrix_sync(&Cs[warpM * 32 + m * 16][warpN * 64 + n * 16],
                                    acc[m][n], LDC1, wmma::mem_row_major);
    __syncthreads();
    #pragma unroll
    for (int q = 0; q < 32; q++) {
        int idx = q * 256 + tid;
        int r = idx >> 6, c2 = (idx & 63) * 2;
        int gi = i0 + r;
        if (gi < N_NODES) {
            float v0 = Cs[r][c2] + c2S[c2];
            float v1 = Cs[r][c2 + 1] + c2S[c2 + 1];
            #pragma unroll
            for (int t = 0; t < 10; t++) {
                float d = demoS[r][t];
                v0 += d * WgbS[t][c2];
                v1 += d * WgbS[t][c2 + 1];
            }
            float dinv = rsqrtf((float)g_deg[gi]);
            *reinterpret_cast<__half2*>(&g_y2[(size_t)gi * DG + c2]) =
                __floats2half2_rn(dinv * v0, dinv * v1);
        }
    }
}

// ---------------- gather (fp16 y) + fused epilogue ----------------
__global__ __launch_bounds__(256) void k_gather(const float* __restrict__ bg,
                                                const float* __restrict__ Wo) {
    int wid = threadIdx.x >> 5, lane = threadIdx.x & 31;
    int node = blockIdx.x * 8 + wid;
    float dot = 0.f;
    if (node < N_NODES) {
        int deg = g_deg[node];
        int beg = g_off[node];
        int cnt = deg - 1;
        float2 raw = *reinterpret_cast<const float2*>(&g_y2[(size_t)node * DG + lane * 4]);
        __half2 h0 = *reinterpret_cast<__half2*>(&raw.x);
        __half2 h1 = *reinterpret_cast<__half2*>(&raw.y);
        float2 f0 = __half22float2(h0), f1 = __half22float2(h1);
        float4 a = make_float4(f0.x, f0.y, f1.x, f1.y);
        #pragma unroll 4
        for (int j = 0; j < cnt; j++) {
            int s = __ldg(&g_es[beg + j]);
            float2 rw = *reinterpret_cast<const float2*>(&g_y2[(size_t)s * DG + lane * 4]);
            __half2 g0 = *reinterpret_cast<__half2*>(&rw.x);
            __half2 g1 = *reinterpret_cast<__half2*>(&rw.y);
            float2 e0 = __half22float2(g0), e1 = __half22float2(g1);
            a.x += e0.x; a.y += e0.y; a.z += e1.x; a.w += e1.y;
        }
        float dinv = rsqrtf((float)deg);
        float4 bgv = *reinterpret_cast<const float4*>(&bg[lane * 4]);
        float4 wv = *reinterpret_cast<const float4*>(&Wo[lane * 4]);
        dot += fmaxf(dinv * a.x + bgv.x, 0.f) * wv.x;
        dot += fmaxf(dinv * a.y + bgv.y, 0.f) * wv.y;
        dot += fmaxf(dinv * a.z + bgv.z, 0.f) * wv.z;
        dot += fmaxf(dinv * a.w + bgv.w, 0.f) * wv.w;
    }
    #pragma unroll
    for (int o = 16; o; o >>= 1) dot += __shfl_down_sync(0xffffffffu, dot, o);
    __shared__ float part[8];
    if (lane == 0) part[wid] = dot;
    __syncthreads();
    if (threadIdx.x == 0) {
        float s = 0.f;
        #pragma unroll
        for (int w = 0; w < 8; w++) s += part[w];
        atomicAdd(&g_acc, (double)s);
    }
}

__global__ void k_fin(const float* __restrict__ bo, float* __restrict__ out) {
    out[0] = (float)(g_acc * (1.0 / (double)N_NODES) + (double)bo[0]);
}

// ---------------- launch (round-14 structure: edge chain on side stream) ----------------
extern "C" void kernel_launch(void* const* d_in, const int* in_sizes, int n_in,
                              void* d_out, int out_size) {
    const float* x  = (const float*)d_in[0];
    const int*   ei = (const int*)d_in[1];
    const float* W1 = (const float*)d_in[2];
    const float* b1 = (const float*)d_in[3];
    const float* W2 = (const float*)d_in[4];
    const float* b2 = (const float*)d_in[5];
    const float* Wg = (const float*)d_in[6];
    const float* bg = (const float*)d_in[7];
    const float* Wo = (const float*)d_in[8];
    const float* bo = (const float*)d_in[9];
    float* out = (float*)d_out;

    static cudaStream_t s1 = nullptr;
    static cudaEvent_t eFork = nullptr, eJoin = nullptr;
    if (s1 == nullptr) {
        cudaStreamCreateWithFlags(&s1, cudaStreamNonBlocking);
        cudaEventCreateWithFlags(&eFork, cudaEventDisableTiming);
        cudaEventCreateWithFlags(&eJoin, cudaEventDisableTiming);
        cudaFuncSetAttribute(k_gemm1, cudaFuncAttributeMaxDynamicSharedMemorySize, DYN1);
        cudaFuncSetAttribute(k_gemm2, cudaFuncAttributeMaxDynamicSharedMemorySize, DYN2);
    }

    cudaEventRecord(eFork, 0);
    cudaStreamWaitEvent(s1, eFork, 0);

    // main chain: split + gemm1 (BM=256, 512 threads)
    k_splitx<<<2048, 256>>>(x);
    k_splitw<<<(1024 * 256 + 255) / 256, 256>>>(W1);
    k_gemm1<<<G1_MBLK * 4, 512, DYN1>>>(b1);

    // side chain: edge prep + weight fold
    k_init<<<(N_NODES + 255) / 256, 256, 0, s1>>>();
    k_pre<<<H1 + 1, 128, 0, s1>>>(W2, Wg, b2);
    k_deg<<<4096, 256, 0, s1>>>(ei);
    k_scan1<<<SCAN_NBLK, SCAN_CHUNK, 0, s1>>>();
    k_scan2<<<1, 128, 0, s1>>>();
    k_scan3<<<SCAN_NBLK, SCAN_CHUNK, 0, s1>>>();
    k_fill<<<4096, 256, 0, s1>>>(ei);
    cudaEventRecord(eJoin, s1);

    cudaStreamWaitEvent(0, eJoin, 0);
    k_gemm2<<<(N_NODES + 127) / 128, 256, DYN2>>>(x, Wg);
    k_gather<<<(N_NODES + 7) / 8, 256>>>(bg, Wo);
    k_fin<<<1, 1>>>(bo, out);
}

// round 17
// speedup vs baseline: 1.0493x; 1.0467x over previous
#include <cuda_runtime.h>
#include <cuda_fp16.h>
#include <mma.h>
#include <cstdint>

using namespace nvcuda;

#define N_NODES 100000
#define N_EDGESC 1600000
#define XDIM 1010
#define SUBJ 1000
#define H1 512
#define H2 256
#define DG 128

// ---------------- static device scratch ----------------
__device__ __half g_xs[(size_t)N_NODES * 1024];   // x hi (K padded to 1024; pad cols stay 0 from static init)
__device__ __half g_w1h[1024 * H1];               // W1 hi
__device__ __half g_hs[(size_t)N_NODES * 512];    // h hi only
__device__ __half g_w23h[H1 * DG];                // folded W2@Wg hi only
__device__ float  g_c2[DG];
__device__ __half g_y2[(size_t)N_NODES * DG];     // y in fp16
__device__ int    g_deg[N_NODES];
__device__ int    g_off[N_NODES];
__device__ int    g_cur[N_NODES];
__device__ int    g_es[N_EDGESC];
__device__ int    g_bsum[128];
__device__ double g_acc;

// ---------------- helpers ----------------
__device__ __forceinline__ uint32_t smem_u32(const void* p) {
    uint32_t a;
    asm("{ .reg .u64 t; cvta.to.shared.u64 t, %1; cvt.u32.u64 %0, t; }" : "=r"(a) : "l"(p));
    return a;
}
#define CP_A16(dst, src, n) \
    asm volatile("cp.async.cg.shared.global [%0], [%1], 16, %2;" :: "r"(dst), "l"(src), "r"(n))
#define CP_COMMIT() asm volatile("cp.async.commit_group;" ::: "memory")
#define CP_WAIT0()  asm volatile("cp.async.wait_group 0;" ::: "memory")
#define CP_WAIT1()  asm volatile("cp.async.wait_group 1;" ::: "memory")

// ---------------- x -> fp16 hi (only real columns; pad stays zero) ----------------
__global__ void k_splitx(const float* __restrict__ x) {
    const long long total = (long long)N_NODES * 500;   // 500 float2 pairs per row
    for (long long id = (long long)blockIdx.x * blockDim.x + threadIdx.x;
         id < total; id += (long long)gridDim.x * blockDim.x) {
        int row = (int)(id / 500);
        int col = (int)(id % 500) * 2;
        float2 v = *reinterpret_cast<const float2*>(&x[(size_t)row * XDIM + col]);
        *reinterpret_cast<__half2*>(&g_xs[(size_t)row * 1024 + col]) = __float22half2_rn(v);
    }
}

// ---------------- W1 -> fp16 hi ----------------
__global__ void k_splitw(const float* __restrict__ W1) {
    int id = blockIdx.x * blockDim.x + threadIdx.x;
    if (id >= 1024 * 256) return;
    int row = id >> 8;
    int col = (id & 255) * 2;
    float2 v = make_float2(0.f, 0.f);
    if (row < SUBJ) v = *reinterpret_cast<const float2*>(&W1[(size_t)row * H1 + col]);
    *reinterpret_cast<__half2*>(&g_w1h[row * H1 + col]) = __float22half2_rn(v);
}

// ---------------- init ----------------
__global__ void k_init() {
    int i = blockIdx.x * blockDim.x + threadIdx.x;
    if (i < N_NODES) g_deg[i] = 1;
    if (i == 0) g_acc = 0.0;
}

// ---------------- weight fold (fp16 hi) ----------------
__global__ void k_pre(const float* __restrict__ W2, const float* __restrict__ Wg,
                      const float* __restrict__ b2) {
    int k = blockIdx.x;
    int j = threadIdx.x;
    if (k < H1) {
        __shared__ float row[H2];
        for (int m = j; m < H2; m += 128) row[m] = W2[k * H2 + m];
        __syncthreads();
        float acc = 0.f;
        #pragma unroll 4
        for (int m = 0; m < H2; m++) acc += row[m] * Wg[m * DG + j];
        g_w23h[k * DG + j] = __float2half_rn(acc);
    } else {
        float acc = 0.f;
        for (int m = 0; m < H2; m++) acc += b2[m] * Wg[m * DG + j];
        g_c2[j] = acc;
    }
}

// ---------------- degree count ----------------
__global__ void k_deg(const int* __restrict__ ei) {
    for (int e = blockIdx.x * blockDim.x + threadIdx.x; e < N_EDGESC;
         e += gridDim.x * blockDim.x) {
        int dst = ei[N_EDGESC + e];
        dst = min(max(dst, 0), N_NODES - 1);
        atomicAdd(&g_deg[dst], 1);
    }
}

// ---------------- multi-block scan ----------------
#define SCAN_CHUNK 1024
#define SCAN_NBLK ((N_NODES + SCAN_CHUNK - 1) / SCAN_CHUNK)  // 98

__global__ void k_scan1() {
    __shared__ int wsum[32];
    int i = blockIdx.x * SCAN_CHUNK + threadIdx.x;
    int v = (i < N_NODES) ? (g_deg[i] - 1) : 0;
    #pragma unroll
    for (int o = 16; o; o >>= 1) v += __shfl_down_sync(0xffffffffu, v, o);
    int lane = threadIdx.x & 31, wid = threadIdx.x >> 5;
    if (lane == 0) wsum[wid] = v;
    __syncthreads();
    if (wid == 0) {
        int t = wsum[lane];
        #pragma unroll
        for (int o = 16; o; o >>= 1) t += __shfl_down_sync(0xffffffffu, t, o);
        if (lane == 0) g_bsum[blockIdx.x] = t;
    }
}

__global__ void k_scan2() {
    __shared__ int wtot[4];
    int tid = threadIdx.x, lane = tid & 31, wid = tid >> 5;
    int v = (tid < SCAN_NBLK) ? g_bsum[tid] : 0;
    int s = v;
    #pragma unroll
    for (int o = 1; o < 32; o <<= 1) {
        int t = __shfl_up_sync(0xffffffffu, s, o);
        if (lane >= o) s += t;
    }
    if (lane == 31) wtot[wid] = s;
    __syncthreads();
    int base = 0;
    for (int w = 0; w < wid; w++) base += wtot[w];
    if (tid < SCAN_NBLK) g_bsum[tid] = base + s - v;
}

__global__ void k_scan3() {
    __shared__ int wpre[32];
    int tid = threadIdx.x, lane = tid & 31, wid = tid >> 5;
    int i = blockIdx.x * SCAN_CHUNK + tid;
    int v = (i < N_NODES) ? (g_deg[i] - 1) : 0;
    int s = v;
    #pragma unroll
    for (int o = 1; o < 32; o <<= 1) {
        int t = __shfl_up_sync(0xffffffffu, s, o);
        if (lane >= o) s += t;
    }
    if (lane == 31) wpre[wid] = s;
    __syncthreads();
    if (wid == 0) {
        int t = wpre[lane];
        #pragma unroll
        for (int o = 1; o < 32; o <<= 1) {
            int u = __shfl_up_sync(0xffffffffu, t, o);
            if (lane >= o) t += u;
        }
        wpre[lane] = t;
    }
    __syncthreads();
    int excl = s - v + (wid > 0 ? wpre[wid - 1] : 0) + g_bsum[blockIdx.x];
    if (i < N_NODES) { g_off[i] = excl; g_cur[i] = excl; }
}

// ---------------- CSR fill ----------------
__global__ void k_fill(const int* __restrict__ ei) {
    for (int e = blockIdx.x * blockDim.x + threadIdx.x; e < N_EDGESC;
         e += gridDim.x * blockDim.x) {
        int src = ei[e];
        int dst = ei[N_EDGESC + e];
        src = min(max(src, 0), N_NODES - 1);
        dst = min(max(dst, 0), N_NODES - 1);
        int pos = atomicAdd(&g_cur[dst], 1);
        g_es[pos] = src;
    }
}

// ================= GEMM1: BM=128 BN=128 BK=64, 256 thr, 3-stage, 1-term (round-14 proven) =================
#define LDA1 72
#define LDB1 136
#define LDC1 136
#define S1_OFF_BH 18432
#define STG1 35840
#define DYN1 107520
#define G1_MBLK ((N_NODES + 127) / 128)   // 782

__device__ __forceinline__ void g1_issue(char* st, int tid, int kt, int rows_left,
                                         const __half* Asrc, const __half* Bsrc) {
    const int k0 = kt * 64;
    const uint32_t ah = smem_u32(st);
    const uint32_t bh = ah + S1_OFF_BH;
    #pragma unroll
    for (int p = 0; p < 4; p++) {
        int idx = tid + p * 256;
        int row = idx >> 3;
        int ch = idx & 7;
        int n = (row < rows_left) ? 16 : 0;
        const __half* s = Asrc + (size_t)row * 1024 + k0 + ch * 8;
        CP_A16(ah + row * (LDA1 * 2) + ch * 16, s, n);
    }
    #pragma unroll
    for (int p = 0; p < 4; p++) {
        int idx = tid + p * 256;
        int row = idx >> 4;
        int ch = idx & 15;
        const __half* sh = Bsrc + (size_t)(k0 + row) * H1 + ch * 8;
        CP_A16(bh + row * (LDB1 * 2) + ch * 16, sh, 16);
    }
    CP_COMMIT();
}

__global__ __launch_bounds__(256) void k_gemm1(const float* __restrict__ b1) {
    extern __shared__ __align__(128) char dyn[];
    const int bx = blockIdx.x;
    const int i0 = (bx >> 2) * 128;
    const int n0 = (bx & 3) * 128;
    const int tid = threadIdx.x;
    const int wid = tid >> 5;
    const int warpM = wid & 3, warpN = wid >> 2;
    const int rows_left = N_NODES - i0;
    const __half* Asrc = g_xs + (size_t)i0 * 1024;
    const __half* Bsrc = g_w1h + n0;

    wmma::fragment<wmma::accumulator, 16, 16, 16, float> acc[2][4];
    #pragma unroll
    for (int m = 0; m < 2; m++)
        #pragma unroll
        for (int n = 0; n < 4; n++) wmma::fill_fragment(acc[m][n], 0.f);

    g1_issue(dyn, tid, 0, rows_left, Asrc, Bsrc);
    g1_issue(dyn + STG1, tid, 1, rows_left, Asrc, Bsrc);

    for (int kt = 0; kt < 16; kt++) {
        if (kt < 14) CP_WAIT1(); else CP_WAIT0();
        __syncthreads();
        if (kt + 2 < 16) g1_issue(dyn + ((kt + 2) % 3) * STG1, tid, kt + 2, rows_left, Asrc, Bsrc);
        char* st = dyn + (kt % 3) * STG1;
        __half (*Ah)[LDA1] = reinterpret_cast<__half(*)[LDA1]>(st);
        __half (*Bh)[LDB1] = reinterpret_cast<__half(*)[LDB1]>(st + S1_OFF_BH);
        #pragma unroll
        for (int kk = 0; kk < 64; kk += 16) {
            wmma::fragment<wmma::matrix_a, 16, 16, 16, __half, wmma::row_major> afH[2];
            #pragma unroll
            for (int m = 0; m < 2; m++)
                wmma::load_matrix_sync(afH[m], &Ah[warpM * 32 + m * 16][kk], LDA1);
            #pragma unroll
            for (int n = 0; n < 4; n++) {
                wmma::fragment<wmma::matrix_b, 16, 16, 16, __half, wmma::row_major> bfH;
                wmma::load_matrix_sync(bfH, &Bh[kk][warpN * 64 + n * 16], LDB1);
                #pragma unroll
                for (int m = 0; m < 2; m++)
                    wmma::mma_sync(acc[m][n], afH[m], bfH, acc[m][n]);
            }
        }
    }

    __syncthreads();
    float (*Cs)[LDC1] = reinterpret_cast<float(*)[LDC1]>(dyn);
    #pragma unroll
    for (int m = 0; m < 2; m++)
        #pragma unroll
        for (int n = 0; n < 4; n++)
            wmma::store_matrix_sync(&Cs[warpM * 32 + m * 16][warpN * 64 + n * 16],
                                    acc[m][n], LDC1, wmma::mem_row_major);
    __syncthreads();
    #pragma unroll
    for (int q = 0; q < 32; q++) {
        int idx = q * 256 + tid;
        int r = idx >> 6, c2 = (idx & 63) * 2;
        int gi = i0 + r;
        if (gi < N_NODES) {
            float2 v;
            v.x = fmaxf(Cs[r][c2] + __ldg(&b1[n0 + c2]), 0.f);
            v.y = fmaxf(Cs[r][c2 + 1] + __ldg(&b1[n0 + c2 + 1]), 0.f);
            *reinterpret_cast<__half2*>(&g_hs[(size_t)gi * 512 + n0 + c2]) = __float22half2_rn(v);
        }
    }
}

// ================= GEMM2 (1-term, BK=32, 3-stage) =================
#define LDA2 40
#define LDB2 136
#define S2_OFF_BH 10240
#define STG2 18944
#define DYN2 69632

__device__ __forceinline__ void g2_issue(char* st, int tid, int kt, int rows_left,
                                         const __half* Asrc) {
    const int k0 = kt * 32;
    const uint32_t ah = smem_u32(st);
    const uint32_t bh = ah + S2_OFF_BH;
    #pragma unroll
    for (int p = 0; p < 2; p++) {
        int idx = tid + p * 256;
        int row = idx >> 2;
        int ch = idx & 3;
        int n = (row < rows_left) ? 16 : 0;
        const __half* s = Asrc + (size_t)row * 512 + k0 + ch * 8;
        CP_A16(ah + row * (LDA2 * 2) + ch * 16, s, n);
    }
    #pragma unroll
    for (int p = 0; p < 2; p++) {
        int idx = tid + p * 256;
        int row = idx >> 4;
        int ch = idx & 15;
        const __half* sh = g_w23h + (size_t)(k0 + row) * DG + ch * 8;
        CP_A16(bh + row * (LDB2 * 2) + ch * 16, sh, 16);
    }
    CP_COMMIT();
}

__global__ __launch_bounds__(256) void k_gemm2(const float* __restrict__ x,
                                               const float* __restrict__ Wg) {
    extern __shared__ __align__(128) char dyn[];
    __shared__ float demoS[128][10];
    __shared__ float WgbS[10][DG];
    __shared__ float c2S[DG];

    const int i0 = blockIdx.x * 128;
    const int tid = threadIdx.x;
    const int wid = tid >> 5;
    const int warpM = wid & 3, warpN = wid >> 2;
    const int rows_left = N_NODES - i0;
    const __half* Asrc = g_hs + (size_t)i0 * 512;

    for (int idx = tid; idx < 128 * 10; idx += 256) {
        int r = idx / 10, t = idx % 10;
        int gi = i0 + r;
        demoS[r][t] = (gi < N_NODES) ? x[(size_t)gi * XDIM + SUBJ + t] : 0.f;
    }
    for (int idx = tid; idx < 10 * DG; idx += 256) {
        int t = idx >> 7, c = idx & 127;
        WgbS[t][c] = Wg[(H2 + t) * DG + c];
    }
    if (tid < DG) c2S[tid] = g_c2[tid];

    wmma::fragment<wmma::accumulator, 16, 16, 16, float> acc[2][4];
    #pragma unroll
    for (int m = 0; m < 2; m++)
        #pragma unroll
        for (int n = 0; n < 4; n++) wmma::fill_fragment(acc[m][n], 0.f);

    g2_issue(dyn, tid, 0, rows_left, Asrc);
    g2_issue(dyn + STG2, tid, 1, rows_left, Asrc);

    for (int kt = 0; kt < 16; kt++) {
        if (kt < 14) CP_WAIT1(); else CP_WAIT0();
        __syncthreads();
        if (kt + 2 < 16) g2_issue(dyn + ((kt + 2) % 3) * STG2, tid, kt + 2, rows_left, Asrc);
        char* st = dyn + (kt % 3) * STG2;
        __half (*Ah)[LDA2] = reinterpret_cast<__half(*)[LDA2]>(st);
        __half (*Bh)[LDB2] = reinterpret_cast<__half(*)[LDB2]>(st + S2_OFF_BH);
        #pragma unroll
        for (int kk = 0; kk < 32; kk += 16) {
            wmma::fragment<wmma::matrix_a, 16, 16, 16, __half, wmma::row_major> afH[2];
            #pragma unroll
            for (int m = 0; m < 2; m++)
                wmma::load_matrix_sync(afH[m], &Ah[warpM * 32 + m * 16][kk], LDA2);
            #pragma unroll
            for (int n = 0; n < 4; n++) {
                wmma::fragment<wmma::matrix_b, 16, 16, 16, __half, wmma::row_major> bfH;
                wmma::load_matrix_sync(bfH, &Bh[kk][warpN * 64 + n * 16], LDB2);
                #pragma unroll
                for (int m = 0; m < 2; m++)
                    wmma::mma_sync(acc[m][n], afH[m], bfH, acc[m][n]);
            }
        }
    }

    __syncthreads();
    float (*Cs)[LDC1] = reinterpret_cast<float(*)[LDC1]>(dyn);
    #pragma unroll
    for (int m = 0; m < 2; m++)
        #pragma unroll
        for (int n = 0; n < 4; n++)
            wmma::store_matrix_sync(&Cs[warpM * 32 + m * 16][warpN * 64 + n * 16],
                                    acc[m][n], LDC1, wmma::mem_row_major);
    __syncthreads();
    #pragma unroll
    for (int q = 0; q < 32; q++) {
        int idx = q * 256 + tid;
        int r = idx >> 6, c2 = (idx & 63) * 2;
        int gi = i0 + r;
        if (gi < N_NODES) {
            float v0 = Cs[r][c2] + c2S[c2];
            float v1 = Cs[r][c2 + 1] + c2S[c2 + 1];
            #pragma unroll
            for (int t = 0; t < 10; t++) {
                float d = demoS[r][t];
                v0 += d * WgbS[t][c2];
                v1 += d * WgbS[t][c2 + 1];
            }
            float dinv = rsqrtf((float)g_deg[gi]);
            *reinterpret_cast<__half2*>(&g_y2[(size_t)gi * DG + c2]) =
                __floats2half2_rn(dinv * v0, dinv * v1);
        }
    }
}

// ---------------- gather (fp16 y) + fused epilogue ----------------
__global__ __launch_bounds__(256) void k_gather(const float* __restrict__ bg,
                                                const float* __restrict__ Wo) {
    int wid = threadIdx.x >> 5, lane = threadIdx.x & 31;
    int node = blockIdx.x * 8 + wid;
    float dot = 0.f;
    if (node < N_NODES) {
        int deg = g_deg[node];
        int beg = g_off[node];
        int cnt = deg - 1;
        float2 raw = *reinterpret_cast<const float2*>(&g_y2[(size_t)node * DG + lane * 4]);
        __half2 h0 = *reinterpret_cast<__half2*>(&raw.x);
        __half2 h1 = *reinterpret_cast<__half2*>(&raw.y);
        float2 f0 = __half22float2(h0), f1 = __half22float2(h1);
        float4 a = make_float4(f0.x, f0.y, f1.x, f1.y);
        #pragma unroll 4
        for (int j = 0; j < cnt; j++) {
            int s = __ldg(&g_es[beg + j]);
            float2 rw = *reinterpret_cast<const float2*>(&g_y2[(size_t)s * DG + lane * 4]);
            __half2 g0 = *reinterpret_cast<__half2*>(&rw.x);
            __half2 g1 = *reinterpret_cast<__half2*>(&rw.y);
            float2 e0 = __half22float2(g0), e1 = __half22float2(g1);
            a.x += e0.x; a.y += e0.y; a.z += e1.x; a.w += e1.y;
        }
        float dinv = rsqrtf((float)deg);
        float4 bgv = *reinterpret_cast<const float4*>(&bg[lane * 4]);
        float4 wv = *reinterpret_cast<const float4*>(&Wo[lane * 4]);
        dot += fmaxf(dinv * a.x + bgv.x, 0.f) * wv.x;
        dot += fmaxf(dinv * a.y + bgv.y, 0.f) * wv.y;
        dot += fmaxf(dinv * a.z + bgv.z, 0.f) * wv.z;
        dot += fmaxf(dinv * a.w + bgv.w, 0.f) * wv.w;
    }
    #pragma unroll
    for (int o = 16; o; o >>= 1) dot += __shfl_down_sync(0xffffffffu, dot, o);
    __shared__ float part[8];
    if (lane == 0) part[wid] = dot;
    __syncthreads();
    if (threadIdx.x == 0) {
        float s = 0.f;
        #pragma unroll
        for (int w = 0; w < 8; w++) s += part[w];
        atomicAdd(&g_acc, (double)s);
    }
}

__global__ void k_fin(const float* __restrict__ bo, float* __restrict__ out) {
    out[0] = (float)(g_acc * (1.0 / (double)N_NODES) + (double)bo[0]);
}

// ---------------- launch (round-14 structure + splitw on side stream) ----------------
extern "C" void kernel_launch(void* const* d_in, const int* in_sizes, int n_in,
                              void* d_out, int out_size) {
    const float* x  = (const float*)d_in[0];
    const int*   ei = (const int*)d_in[1];
    const float* W1 = (const float*)d_in[2];
    const float* b1 = (const float*)d_in[3];
    const float* W2 = (const float*)d_in[4];
    const float* b2 = (const float*)d_in[5];
    const float* Wg = (const float*)d_in[6];
    const float* bg = (const float*)d_in[7];
    const float* Wo = (const float*)d_in[8];
    const float* bo = (const float*)d_in[9];
    float* out = (float*)d_out;

    static cudaStream_t s1 = nullptr;
    static cudaEvent_t eFork = nullptr, eJoin = nullptr, eW = nullptr;
    if (s1 == nullptr) {
        cudaStreamCreateWithFlags(&s1, cudaStreamNonBlocking);
        cudaEventCreateWithFlags(&eFork, cudaEventDisableTiming);
        cudaEventCreateWithFlags(&eJoin, cudaEventDisableTiming);
        cudaEventCreateWithFlags(&eW, cudaEventDisableTiming);
        cudaFuncSetAttribute(k_gemm1, cudaFuncAttributeMaxDynamicSharedMemorySize, DYN1);
        cudaFuncSetAttribute(k_gemm2, cudaFuncAttributeMaxDynamicSharedMemorySize, DYN2);
    }

    cudaEventRecord(eFork, 0);
    cudaStreamWaitEvent(s1, eFork, 0);

    // side chain: W1 convert first (gemm1 waits on it), then edge prep
    k_splitw<<<(1024 * 256 + 255) / 256, 256, 0, s1>>>(W1);
    cudaEventRecord(eW, s1);
    k_init<<<(N_NODES + 255) / 256, 256, 0, s1>>>();
    k_pre<<<H1 + 1, 128, 0, s1>>>(W2, Wg, b2);
    k_deg<<<4096, 256, 0, s1>>>(ei);
    k_scan1<<<SCAN_NBLK, SCAN_CHUNK, 0, s1>>>();
    k_scan2<<<1, 128, 0, s1>>>();
    k_scan3<<<SCAN_NBLK, SCAN_CHUNK, 0, s1>>>();
    k_fill<<<4096, 256, 0, s1>>>(ei);
    cudaEventRecord(eJoin, s1);

    // main chain: x convert, then gemm1 (after W1 ready)
    k_splitx<<<2048, 256>>>(x);
    cudaStreamWaitEvent(0, eW, 0);
    k_gemm1<<<G1_MBLK * 4, 256, DYN1>>>(b1);

    // join: gemm2 needs g_deg/g_w23h/g_c2; gather needs g_off/g_es
    cudaStreamWaitEvent(0, eJoin, 0);
    k_gemm2<<<(N_NODES + 127) / 128, 256, DYN2>>>(x, Wg);
    k_gather<<<(N_NODES + 7) / 8, 256>>>(bg, Wo);
    k_fin<<<1, 1>>>(bo, out);
}